// round 1
// baseline (speedup 1.0000x reference)
#include <cuda_runtime.h>
#include <cuda_bf16.h>
#include <cstdint>

// Problem constants
#define CUR   1024
#define FULL  2048
#define BSZ   4
#define DMODEL 1024
#define HN    16
#define HD    64
#define PREV  (FULL - CUR)      // 1024
#define ZB    (BSZ * HN)        // 64 batched heads
#define SCALE 0.125f            // 1/sqrt(64)

// ---------------------------------------------------------------------------
// Scratch (static device globals; no runtime allocation allowed)
// ---------------------------------------------------------------------------
__device__ float g_kv [ (size_t)FULL * BSZ * 2 * HN * HD ];        // 8192 x 2048
__device__ float g_q  [ (size_t)CUR * BSZ * HN * HD ];             // 4096 x 1024
__device__ float g_r  [ (size_t)FULL * HN * HD ];                  // 2048 x 1024
__device__ float g_ctx[ (size_t)CUR * BSZ * HN * HD ];             // 4096 x 1024
__device__ float g_scores[ (size_t)ZB * CUR * FULL ];              // 64 x 1024 x 2048 (content, then probs)
__device__ float g_pos   [ (size_t)ZB * CUR * FULL ];              // 64 x 1024 x 2048 (unshifted position)

// ---------------------------------------------------------------------------
// Generic SGEMM + bias: C[M,N] = A[M,K] @ B[K,N] + bias[N]
// 128x128 tile, BK=8, 256 threads, 8x8 per thread. M,N mult of 128, K mult of 8.
// ---------------------------------------------------------------------------
__global__ __launch_bounds__(256) void sgemm128_bias(
    const float* __restrict__ A, const float* __restrict__ B,
    const float* __restrict__ bias, float* __restrict__ C,
    int M, int N, int K)
{
    __shared__ float sA[8][128];
    __shared__ float sB[8][128];
    int tid = threadIdx.x;
    int tx = tid & 15, ty = tid >> 4;
    int m0 = blockIdx.y * 128, n0 = blockIdx.x * 128;

    float acc[8][8];
#pragma unroll
    for (int i = 0; i < 8; i++)
#pragma unroll
        for (int j = 0; j < 8; j++) acc[i][j] = 0.f;

    for (int k0 = 0; k0 < K; k0 += 8) {
        {   // A tile 128m x 8k -> sA[k][m]
            int m = tid >> 1;
            int k = (tid & 1) * 4;
            float4 v = *reinterpret_cast<const float4*>(A + (size_t)(m0 + m) * K + k0 + k);
            sA[k + 0][m] = v.x; sA[k + 1][m] = v.y; sA[k + 2][m] = v.z; sA[k + 3][m] = v.w;
        }
        {   // B tile 8k x 128n -> sB[k][n]
            int k = tid >> 5;
            int n = (tid & 31) * 4;
            float4 v = *reinterpret_cast<const float4*>(B + (size_t)(k0 + k) * N + n0 + n);
            *reinterpret_cast<float4*>(&sB[k][n]) = v;
        }
        __syncthreads();
#pragma unroll
        for (int k = 0; k < 8; k++) {
            float a[8], bb[8];
#pragma unroll
            for (int i = 0; i < 8; i++) a[i]  = sA[k][ty * 8 + i];
#pragma unroll
            for (int j = 0; j < 8; j++) bb[j] = sB[k][tx * 8 + j];
#pragma unroll
            for (int i = 0; i < 8; i++)
#pragma unroll
                for (int j = 0; j < 8; j++) acc[i][j] += a[i] * bb[j];
        }
        __syncthreads();
    }
#pragma unroll
    for (int i = 0; i < 8; i++) {
        size_t m = (size_t)(m0 + ty * 8 + i);
#pragma unroll
        for (int j = 0; j < 8; j++) {
            int n = n0 + tx * 8 + j;
            C[m * N + n] = acc[i][j] + bias[n];
        }
    }
}

// ---------------------------------------------------------------------------
// Attention scores (content or position, UNshifted):
//   out[z, i, j] = sum_d (q[i,b,h,d] + uv[h,d]) * B(j,d)
//   content: B(j,d) = kv[(j*BSZ+b)*2048 + h*64 + d]
//   position: B(j,d) = r[j*1024 + h*64 + d]
// 64x64 output tile per block, K = 64 in chunks of 16.
// ---------------------------------------------------------------------------
__global__ __launch_bounds__(256) void score_kernel(
    const float* __restrict__ q, const float* __restrict__ uv,
    const float* __restrict__ src, float* __restrict__ out, int isPos)
{
    int z = blockIdx.z;
    int b = z >> 4, h = z & 15;
    const float* A0   = q + b * DMODEL + h * HD;           // A(i,d) = A0[i*4096 + d]
    const float* bias = uv + h * HD;
    const float* B0   = isPos ? (src + h * HD) : (src + b * 2048 + h * HD);
    int bstr          = isPos ? (HN * HD) : (BSZ * 2 * HN * HD);   // 1024 or 8192

    int i0 = blockIdx.y * 64, j0 = blockIdx.x * 64;
    float* C0 = out + (size_t)z * CUR * FULL;

    __shared__ float sA[16][64];  // [d][i]
    __shared__ float sB[16][64];  // [d][j]
    int tid = threadIdx.x;
    int tx = tid & 15, ty = tid >> 4;

    float acc[4][4];
#pragma unroll
    for (int i = 0; i < 4; i++)
#pragma unroll
        for (int j = 0; j < 4; j++) acc[i][j] = 0.f;

    for (int d0 = 0; d0 < HD; d0 += 16) {
        {
            int ii = tid >> 2;
            int dd = (tid & 3) * 4;
            float4 v  = *reinterpret_cast<const float4*>(A0 + (size_t)(i0 + ii) * (BSZ * DMODEL) + d0 + dd);
            float4 bv = *reinterpret_cast<const float4*>(bias + d0 + dd);
            sA[dd + 0][ii] = v.x + bv.x; sA[dd + 1][ii] = v.y + bv.y;
            sA[dd + 2][ii] = v.z + bv.z; sA[dd + 3][ii] = v.w + bv.w;
        }
        {
            int jj = tid >> 2;
            int dd = (tid & 3) * 4;
            float4 v = *reinterpret_cast<const float4*>(B0 + (size_t)(j0 + jj) * bstr + d0 + dd);
            sB[dd + 0][jj] = v.x; sB[dd + 1][jj] = v.y;
            sB[dd + 2][jj] = v.z; sB[dd + 3][jj] = v.w;
        }
        __syncthreads();
#pragma unroll
        for (int k = 0; k < 16; k++) {
            float a[4], bb[4];
#pragma unroll
            for (int i = 0; i < 4; i++) a[i]  = sA[k][ty * 4 + i];
#pragma unroll
            for (int j = 0; j < 4; j++) bb[j] = sB[k][tx * 4 + j];
#pragma unroll
            for (int i = 0; i < 4; i++)
#pragma unroll
                for (int j = 0; j < 4; j++) acc[i][j] += a[i] * bb[j];
        }
        __syncthreads();
    }
#pragma unroll
    for (int i = 0; i < 4; i++) {
        size_t row = (size_t)(i0 + ty * 4 + i) * FULL;
#pragma unroll
        for (int j = 0; j < 4; j++)
            C0[row + j0 + tx * 4 + j] = acc[i][j];
    }
}

// ---------------------------------------------------------------------------
// Fused rel_shift gather + mask + softmax (in place into g_scores).
// Row (z, i): valid j in [0, i+PREV]; shifted position index = j + 1023 - i.
// One block of 256 threads per row, 8 elements per thread.
// ---------------------------------------------------------------------------
__global__ __launch_bounds__(256) void softmax_kernel(
    const float* __restrict__ cont, const float* __restrict__ pos,
    float* __restrict__ out)
{
    int i = blockIdx.x;        // 0..1023
    int z = blockIdx.y;        // 0..63
    int tid = threadIdx.x;
    size_t rowOff = ((size_t)z * CUR + i) * FULL;
    const float* c = cont + rowOff;
    const float* p = pos + rowOff;
    int jmax  = i + PREV;      // inclusive
    int shift = CUR - 1 - i;   // 1023 - i

    float vals[8];
    float mx = -1e30f;
#pragma unroll
    for (int it = 0; it < 8; it++) {
        int j = tid + it * 256;
        float s = -1e30f;
        if (j <= jmax) s = (c[j] + p[j + shift]) * SCALE;
        vals[it] = s;
        mx = fmaxf(mx, s);
    }
    __shared__ float redm[8];
    __shared__ float reds[8];
#pragma unroll
    for (int o = 16; o; o >>= 1) mx = fmaxf(mx, __shfl_xor_sync(0xffffffffu, mx, o));
    if ((tid & 31) == 0) redm[tid >> 5] = mx;
    __syncthreads();
    mx = redm[0];
#pragma unroll
    for (int w = 1; w < 8; w++) mx = fmaxf(mx, redm[w]);

    float sum = 0.f;
#pragma unroll
    for (int it = 0; it < 8; it++) {
        float e = __expf(vals[it] - mx);   // masked lanes underflow to 0
        vals[it] = e;
        sum += e;
    }
#pragma unroll
    for (int o = 16; o; o >>= 1) sum += __shfl_xor_sync(0xffffffffu, sum, o);
    if ((tid & 31) == 0) reds[tid >> 5] = sum;
    __syncthreads();
    sum = 0.f;
#pragma unroll
    for (int w = 0; w < 8; w++) sum += reds[w];
    float inv = 1.f / sum;

    float* o = out + rowOff;
#pragma unroll
    for (int it = 0; it < 8; it++) {
        int j = tid + it * 256;
        o[j] = (j <= jmax) ? vals[it] * inv : 0.f;
    }
}

// ---------------------------------------------------------------------------
// Context: ctx[(i*BSZ+b)*1024 + h*64 + d] = sum_j probs[z,i,j] * val(j,d)
//   val(j,d) = kv[(j*BSZ+b)*2048 + 1024 + h*64 + d]
// Block: 64 i-rows x 64 d-cols (all of HD), K=2048 in chunks of 16.
// ---------------------------------------------------------------------------
__global__ __launch_bounds__(256) void ctx_kernel(
    const float* __restrict__ probs, const float* __restrict__ kv,
    float* __restrict__ ctx)
{
    int z = blockIdx.y;
    int b = z >> 4, h = z & 15;
    int i0 = blockIdx.x * 64;
    const float* A0 = probs + (size_t)z * CUR * FULL + (size_t)i0 * FULL; // A(i,j)=A0[i*2048+j]
    const float* B0 = kv + (size_t)b * 2048 + HN * HD + h * HD;          // B(j,d)=B0[j*8192+d]

    __shared__ float sA[16][64];  // [j][i]
    __shared__ float sB[16][64];  // [j][d]
    int tid = threadIdx.x;
    int tx = tid & 15, ty = tid >> 4;

    float acc[4][4];
#pragma unroll
    for (int i = 0; i < 4; i++)
#pragma unroll
        for (int j = 0; j < 4; j++) acc[i][j] = 0.f;

    for (int j0 = 0; j0 < FULL; j0 += 16) {
        {
            int ii = tid >> 2;
            int jj = (tid & 3) * 4;
            float4 v = *reinterpret_cast<const float4*>(A0 + (size_t)ii * FULL + j0 + jj);
            sA[jj + 0][ii] = v.x; sA[jj + 1][ii] = v.y;
            sA[jj + 2][ii] = v.z; sA[jj + 3][ii] = v.w;
        }
        {
            int jj = tid >> 4;
            int dd = (tid & 15) * 4;
            float4 v = *reinterpret_cast<const float4*>(B0 + (size_t)(j0 + jj) * (BSZ * 2 * HN * HD) + dd);
            *reinterpret_cast<float4*>(&sB[jj][dd]) = v;
        }
        __syncthreads();
#pragma unroll
        for (int k = 0; k < 16; k++) {
            float a[4], bb[4];
#pragma unroll
            for (int i = 0; i < 4; i++) a[i]  = sA[k][ty * 4 + i];
#pragma unroll
            for (int j = 0; j < 4; j++) bb[j] = sB[k][tx * 4 + j];
#pragma unroll
            for (int i = 0; i < 4; i++)
#pragma unroll
                for (int j = 0; j < 4; j++) acc[i][j] += a[i] * bb[j];
        }
        __syncthreads();
    }
#pragma unroll
    for (int i = 0; i < 4; i++) {
        size_t row = (size_t)((i0 + ty * 4 + i) * BSZ + b) * DMODEL + h * HD;
#pragma unroll
        for (int j = 0; j < 4; j++)
            ctx[row + tx * 4 + j] = acc[i][j];
    }
}

// ---------------------------------------------------------------------------
// Launch
// Inputs (metadata order):
//  0 inputs (1024,4,1024)  1 pos_embedding (2048,1,1024)  2 full_input (2048,4,1024)
//  3 u (16,64)  4 v (16,64)  5 mask (unused)
//  6 W_kv (1024,2048)  7 b_kv (2048)  8 W_q (1024,1024)  9 b_q (1024)
// 10 W_pos (1024,1024) 11 b_pos (1024) 12 W_proj (1024,1024) 13 b_proj (1024)
// ---------------------------------------------------------------------------
extern "C" void kernel_launch(void* const* d_in, const int* in_sizes, int n_in,
                              void* d_out, int out_size)
{
    const float* inputs  = (const float*)d_in[0];
    const float* pos_emb = (const float*)d_in[1];
    const float* full_in = (const float*)d_in[2];
    const float* u       = (const float*)d_in[3];
    const float* v       = (const float*)d_in[4];
    const float* W_kv    = (const float*)d_in[6];
    const float* b_kv    = (const float*)d_in[7];
    const float* W_q     = (const float*)d_in[8];
    const float* b_q     = (const float*)d_in[9];
    const float* W_pos   = (const float*)d_in[10];
    const float* b_pos   = (const float*)d_in[11];
    const float* W_proj  = (const float*)d_in[12];
    const float* b_proj  = (const float*)d_in[13];
    float* out = (float*)d_out;

    float *kv, *q, *r, *ctx, *scores, *pos;
    cudaGetSymbolAddress((void**)&kv,     g_kv);
    cudaGetSymbolAddress((void**)&q,      g_q);
    cudaGetSymbolAddress((void**)&r,      g_r);
    cudaGetSymbolAddress((void**)&ctx,    g_ctx);
    cudaGetSymbolAddress((void**)&scores, g_scores);
    cudaGetSymbolAddress((void**)&pos,    g_pos);

    // 1) kv = full_input @ W_kv + b_kv      (8192 x 2048 x 1024)
    sgemm128_bias<<<dim3(2048 / 128, 8192 / 128), 256>>>(full_in, W_kv, b_kv, kv, 8192, 2048, 1024);
    // 2) q  = inputs @ W_q + b_q            (4096 x 1024 x 1024)
    sgemm128_bias<<<dim3(1024 / 128, 4096 / 128), 256>>>(inputs, W_q, b_q, q, 4096, 1024, 1024);
    // 3) r  = pos_embedding @ W_pos + b_pos (2048 x 1024 x 1024)
    sgemm128_bias<<<dim3(1024 / 128, 2048 / 128), 256>>>(pos_emb, W_pos, b_pos, r, 2048, 1024, 1024);

    // 4) content scores: (q+u) . k
    score_kernel<<<dim3(FULL / 64, CUR / 64, ZB), 256>>>(q, u, kv, scores, 0);
    // 5) position scores (unshifted): (q+v) . r
    score_kernel<<<dim3(FULL / 64, CUR / 64, ZB), 256>>>(q, v, r, pos, 1);

    // 6) shift + mask + softmax (in place into scores)
    softmax_kernel<<<dim3(CUR, ZB), 256>>>(scores, pos, scores);

    // 7) ctx = probs @ val
    ctx_kernel<<<dim3(CUR / 64, ZB), 256>>>(scores, kv, ctx);

    // 8) out = ctx @ W_proj + b_proj        (4096 x 1024 x 1024)
    sgemm128_bias<<<dim3(1024 / 128, 4096 / 128), 256>>>(ctx, W_proj, b_proj, out, 4096, 1024, 1024);

    (void)in_sizes; (void)n_in; (void)out_size;
}

// round 2
// speedup vs baseline: 2.5124x; 2.5124x over previous
#include <cuda_runtime.h>
#include <cuda_bf16.h>
#include <mma.h>
#include <cstdint>

using namespace nvcuda;

// Problem constants
#define CUR    1024
#define FULL   2048
#define BSZ    4
#define DMODEL 1024
#define HN     16
#define HD     64
#define PREV   (FULL - CUR)      // 1024
#define ZB     (BSZ * HN)        // 64 batched heads
#define SCALE  0.125f            // 1/sqrt(64)

// ---------------------------------------------------------------------------
// Scratch (static device globals; no runtime allocation allowed)
// ---------------------------------------------------------------------------
__device__ float g_kv [ (size_t)FULL * BSZ * 2 * HN * HD ];   // 8192 x 2048
__device__ float g_q  [ (size_t)CUR * BSZ * HN * HD ];        // 4096 x 1024 (no bias)
__device__ float g_qu [ (size_t)CUR * BSZ * HN * HD ];        // q + b_q + u
__device__ float g_qv [ (size_t)CUR * BSZ * HN * HD ];        // q + b_q + v
__device__ float g_r  [ (size_t)FULL * HN * HD ];             // 2048 x 1024 (no bias)
__device__ float g_ctx[ (size_t)CUR * BSZ * HN * HD ];        // 4096 x 1024
__device__ float g_scores[ (size_t)ZB * CUR * FULL ];         // content -> probs
__device__ float g_pos   [ (size_t)ZB * CUR * FULL ];         // unshifted position
__device__ float g_beff[ DMODEL ];                            // effective proj bias

// ---------------------------------------------------------------------------
// Generic TF32 GEMM: C[M,N] = A[M,K] @ B[K,N]   (row-major everything)
// 128x128 tile, KC=32, 256 threads, 8 warps each 64x32 (4x2 m16n16k8 frags).
// M,N multiples of 128, K multiple of 32.
// ---------------------------------------------------------------------------
__global__ __launch_bounds__(256) void gemm_tf32(
    const float* __restrict__ A, const float* __restrict__ B,
    float* __restrict__ C, int M, int N, int K)
{
    __shared__ float sA[128][40];   // [m][k]
    __shared__ float sB[32][136];   // [k][n]
    int tid = threadIdx.x, warp = tid >> 5;
    int wm = warp >> 2, wn = warp & 3;            // warp tile 64x32
    int m0 = blockIdx.y * 128, n0 = blockIdx.x * 128;

    wmma::fragment<wmma::accumulator, 16, 16, 8, float> acc[4][2];
#pragma unroll
    for (int i = 0; i < 4; i++)
#pragma unroll
        for (int j = 0; j < 2; j++) wmma::fill_fragment(acc[i][j], 0.f);

    int am = tid >> 1,  ak = (tid & 1) * 16;
    int bk = tid >> 3,  bn = (tid & 7) * 16;

    for (int k0 = 0; k0 < K; k0 += 32) {
        const float* ap = A + (size_t)(m0 + am) * K + k0 + ak;
#pragma unroll
        for (int s = 0; s < 4; s++) {
            float4 v = *reinterpret_cast<const float4*>(ap + 4 * s);
            sA[am][ak + 4 * s + 0] = wmma::__float_to_tf32(v.x);
            sA[am][ak + 4 * s + 1] = wmma::__float_to_tf32(v.y);
            sA[am][ak + 4 * s + 2] = wmma::__float_to_tf32(v.z);
            sA[am][ak + 4 * s + 3] = wmma::__float_to_tf32(v.w);
        }
        const float* bp = B + (size_t)(k0 + bk) * N + n0 + bn;
#pragma unroll
        for (int s = 0; s < 4; s++) {
            float4 v = *reinterpret_cast<const float4*>(bp + 4 * s);
            sB[bk][bn + 4 * s + 0] = wmma::__float_to_tf32(v.x);
            sB[bk][bn + 4 * s + 1] = wmma::__float_to_tf32(v.y);
            sB[bk][bn + 4 * s + 2] = wmma::__float_to_tf32(v.z);
            sB[bk][bn + 4 * s + 3] = wmma::__float_to_tf32(v.w);
        }
        __syncthreads();
#pragma unroll
        for (int kk = 0; kk < 4; kk++) {
            wmma::fragment<wmma::matrix_a, 16, 16, 8, wmma::precision::tf32, wmma::row_major> af[4];
            wmma::fragment<wmma::matrix_b, 16, 16, 8, wmma::precision::tf32, wmma::row_major> bf[2];
#pragma unroll
            for (int i = 0; i < 4; i++)
                wmma::load_matrix_sync(af[i], &sA[wm * 64 + i * 16][kk * 8], 40);
#pragma unroll
            for (int j = 0; j < 2; j++)
                wmma::load_matrix_sync(bf[j], &sB[kk * 8][wn * 32 + j * 16], 136);
#pragma unroll
            for (int i = 0; i < 4; i++)
#pragma unroll
                for (int j = 0; j < 2; j++)
                    wmma::mma_sync(acc[i][j], af[i], bf[j], acc[i][j]);
        }
        __syncthreads();
    }
#pragma unroll
    for (int i = 0; i < 4; i++)
#pragma unroll
        for (int j = 0; j < 2; j++)
            wmma::store_matrix_sync(
                C + (size_t)(m0 + wm * 64 + i * 16) * N + n0 + wn * 32 + j * 16,
                acc[i][j], N, wmma::mem_row_major);
}

// ---------------------------------------------------------------------------
// qu = q + (b_q + u)[n],  qv = q + (b_q + v)[n]   over 4096x1024
// ---------------------------------------------------------------------------
__global__ __launch_bounds__(256) void quv_kernel(
    const float* __restrict__ q, const float* __restrict__ b_q,
    const float* __restrict__ u, const float* __restrict__ v,
    float* __restrict__ qu, float* __restrict__ qv)
{
    int idx = blockIdx.x * 256 + threadIdx.x;          // float4 index
    int n4 = idx & 255;
    float4 qq = reinterpret_cast<const float4*>(q)[idx];
    float4 bb = reinterpret_cast<const float4*>(b_q)[n4];
    float4 uu = reinterpret_cast<const float4*>(u)[n4];
    float4 vv = reinterpret_cast<const float4*>(v)[n4];
    float4 a, c;
    a.x = qq.x + bb.x + uu.x; a.y = qq.y + bb.y + uu.y;
    a.z = qq.z + bb.z + uu.z; a.w = qq.w + bb.w + uu.w;
    c.x = qq.x + bb.x + vv.x; c.y = qq.y + bb.y + vv.y;
    c.z = qq.z + bb.z + vv.z; c.w = qq.w + bb.w + vv.w;
    reinterpret_cast<float4*>(qu)[idx] = a;
    reinterpret_cast<float4*>(qv)[idx] = c;
}

// ---------------------------------------------------------------------------
// b_eff[n] = b_proj[n] + sum_m b_kv[1024+m] * W_proj[m,n]
// ---------------------------------------------------------------------------
__global__ __launch_bounds__(256) void beff_kernel(
    const float* __restrict__ b_kv, const float* __restrict__ W_proj,
    const float* __restrict__ b_proj, float* __restrict__ beff)
{
    int n = blockIdx.x * 256 + threadIdx.x;
    float acc = b_proj[n];
    for (int m = 0; m < DMODEL; m++)
        acc += b_kv[DMODEL + m] * W_proj[(size_t)m * DMODEL + n];
    beff[n] = acc;
}

__global__ __launch_bounds__(256) void bias_add_kernel(
    float* __restrict__ out, const float* __restrict__ beff)
{
    int idx = blockIdx.x * 256 + threadIdx.x;          // float4 index
    int n4 = idx & 255;
    float4 o = reinterpret_cast<float4*>(out)[idx];
    float4 b = reinterpret_cast<const float4*>(beff)[n4];
    o.x += b.x; o.y += b.y; o.z += b.z; o.w += b.w;
    reinterpret_cast<float4*>(out)[idx] = o;
}

// ---------------------------------------------------------------------------
// Score GEMM (content or unshifted position), TF32:
//   OUT[z,i,j] = sum_d A(i,d) * B(j,d)
//   content: A=qu, B(j,d)=kv[(j*BSZ+b)*2048 + h*64 + d]   (ld 8192)
//   pos:     A=qv, B(j,d)=r [j*1024 + h*64 + d]           (ld 1024)
// 128x128 tile per block, K=64 in chunks of 32.
// Analytic skips: content blocks fully masked; pos blocks never read.
// ---------------------------------------------------------------------------
__global__ __launch_bounds__(256) void score_tf32(
    const float* __restrict__ QU, const float* __restrict__ SRC,
    float* __restrict__ OUT, int isPos)
{
    int i0 = blockIdx.y * 128, j0 = blockIdx.x * 128;
    if (!isPos && j0 >= i0 + 1152) return;                 // all masked
    if (isPos && (i0 + j0 + 254) < 1023) return;           // never read after shift
    int z = blockIdx.z;
    int b = z >> 4, h = z & 15;
    const float* A0 = QU + b * DMODEL + h * HD;            // ld 4096
    const float* B0 = isPos ? (SRC + h * HD) : (SRC + b * 2048 + h * HD);
    size_t ldB = isPos ? (size_t)(HN * HD) : (size_t)(BSZ * 2 * HN * HD);

    __shared__ float sA[128][40];   // [i][d]
    __shared__ float sB[128][40];   // [j][d]
    int tid = threadIdx.x, warp = tid >> 5;
    int wm = warp >> 2, wn = warp & 3;                     // warp tile 64x32

    wmma::fragment<wmma::accumulator, 16, 16, 8, float> acc[4][2];
#pragma unroll
    for (int i = 0; i < 4; i++)
#pragma unroll
        for (int j = 0; j < 2; j++) wmma::fill_fragment(acc[i][j], 0.f);

    int rm = tid >> 1, rk = (tid & 1) * 16;

    for (int d0 = 0; d0 < HD; d0 += 32) {
        const float* ap = A0 + (size_t)(i0 + rm) * (BSZ * DMODEL) + d0 + rk;
#pragma unroll
        for (int s = 0; s < 4; s++) {
            float4 v = *reinterpret_cast<const float4*>(ap + 4 * s);
            sA[rm][rk + 4 * s + 0] = wmma::__float_to_tf32(v.x);
            sA[rm][rk + 4 * s + 1] = wmma::__float_to_tf32(v.y);
            sA[rm][rk + 4 * s + 2] = wmma::__float_to_tf32(v.z);
            sA[rm][rk + 4 * s + 3] = wmma::__float_to_tf32(v.w);
        }
        const float* bp = B0 + (size_t)(j0 + rm) * ldB + d0 + rk;
#pragma unroll
        for (int s = 0; s < 4; s++) {
            float4 v = *reinterpret_cast<const float4*>(bp + 4 * s);
            sB[rm][rk + 4 * s + 0] = wmma::__float_to_tf32(v.x);
            sB[rm][rk + 4 * s + 1] = wmma::__float_to_tf32(v.y);
            sB[rm][rk + 4 * s + 2] = wmma::__float_to_tf32(v.z);
            sB[rm][rk + 4 * s + 3] = wmma::__float_to_tf32(v.w);
        }
        __syncthreads();
#pragma unroll
        for (int kk = 0; kk < 4; kk++) {
            wmma::fragment<wmma::matrix_a, 16, 16, 8, wmma::precision::tf32, wmma::row_major> af[4];
            wmma::fragment<wmma::matrix_b, 16, 16, 8, wmma::precision::tf32, wmma::col_major> bf[2];
#pragma unroll
            for (int i = 0; i < 4; i++)
                wmma::load_matrix_sync(af[i], &sA[wm * 64 + i * 16][kk * 8], 40);
#pragma unroll
            for (int j = 0; j < 2; j++)
                wmma::load_matrix_sync(bf[j], &sB[wn * 32 + j * 16][kk * 8], 40);
#pragma unroll
            for (int i = 0; i < 4; i++)
#pragma unroll
                for (int j = 0; j < 2; j++)
                    wmma::mma_sync(acc[i][j], af[i], bf[j], acc[i][j]);
        }
        __syncthreads();
    }
    float* C0 = OUT + (size_t)z * CUR * FULL;
#pragma unroll
    for (int i = 0; i < 4; i++)
#pragma unroll
        for (int j = 0; j < 2; j++)
            wmma::store_matrix_sync(
                C0 + (size_t)(i0 + wm * 64 + i * 16) * FULL + j0 + wn * 32 + j * 16,
                acc[i][j], FULL, wmma::mem_row_major);
}

// ---------------------------------------------------------------------------
// Fused rel_shift gather + mask + softmax (in place into g_scores).
// ---------------------------------------------------------------------------
__global__ __launch_bounds__(256) void softmax_kernel(
    const float* __restrict__ cont, const float* __restrict__ pos,
    float* __restrict__ out)
{
    int i = blockIdx.x;
    int z = blockIdx.y;
    int tid = threadIdx.x;
    size_t rowOff = ((size_t)z * CUR + i) * FULL;
    const float* c = cont + rowOff;
    const float* p = pos + rowOff;
    int jmax  = i + PREV;
    int shift = CUR - 1 - i;

    float vals[8];
    float mx = -1e30f;
#pragma unroll
    for (int it = 0; it < 8; it++) {
        int j = tid + it * 256;
        float s = -1e30f;
        if (j <= jmax) s = (c[j] + p[j + shift]) * SCALE;
        vals[it] = s;
        mx = fmaxf(mx, s);
    }
    __shared__ float redm[8];
    __shared__ float reds[8];
#pragma unroll
    for (int o = 16; o; o >>= 1) mx = fmaxf(mx, __shfl_xor_sync(0xffffffffu, mx, o));
    if ((tid & 31) == 0) redm[tid >> 5] = mx;
    __syncthreads();
    mx = redm[0];
#pragma unroll
    for (int w = 1; w < 8; w++) mx = fmaxf(mx, redm[w]);

    float sum = 0.f;
#pragma unroll
    for (int it = 0; it < 8; it++) {
        float e = __expf(vals[it] - mx);
        vals[it] = e;
        sum += e;
    }
#pragma unroll
    for (int o = 16; o; o >>= 1) sum += __shfl_xor_sync(0xffffffffu, sum, o);
    if ((tid & 31) == 0) reds[tid >> 5] = sum;
    __syncthreads();
    sum = 0.f;
#pragma unroll
    for (int w = 0; w < 8; w++) sum += reds[w];
    float inv = 1.f / sum;

    float* o = out + rowOff;
#pragma unroll
    for (int it = 0; it < 8; it++) {
        int j = tid + it * 256;
        o[j] = (j <= jmax) ? vals[it] * inv : 0.f;
    }
}

// ---------------------------------------------------------------------------
// Context GEMM, TF32: ctx[(i*BSZ+b)*1024 + h*64 + d] = sum_j P[z,i,j] val(j,d)
//   val(j,d) = kv[(j*BSZ+b)*2048 + 1024 + h*64 + d]     (ld 8192)
// Block tile 128(i) x 64(d); K chunks of 32; K truncated at i0+1152 (probs=0 beyond).
// 8 warps each 32x32 (2x2 frags).
// ---------------------------------------------------------------------------
__global__ __launch_bounds__(256) void ctx_tf32(
    const float* __restrict__ probs, const float* __restrict__ kv,
    float* __restrict__ ctx)
{
    int z = blockIdx.y;
    int b = z >> 4, h = z & 15;
    int i0 = blockIdx.x * 128;
    const float* A0 = probs + (size_t)z * CUR * FULL;                  // ld 2048
    const float* B0 = kv + (size_t)b * 2048 + HN * HD + h * HD;        // ld 8192

    __shared__ float sA[128][40];   // [i][j]
    __shared__ float sB[32][72];    // [j][d]
    int tid = threadIdx.x, warp = tid >> 5;
    int wm = warp >> 1, wn = warp & 1;                                 // warp 32x32

    wmma::fragment<wmma::accumulator, 16, 16, 8, float> acc[2][2];
#pragma unroll
    for (int i = 0; i < 2; i++)
#pragma unroll
        for (int j = 0; j < 2; j++) wmma::fill_fragment(acc[i][j], 0.f);

    int am = tid >> 1, aj = (tid & 1) * 16;
    int bj = tid >> 3, bd = (tid & 7) * 8;

    int kmax = i0 + 1152;  if (kmax > FULL) kmax = FULL;

    for (int k0 = 0; k0 < kmax; k0 += 32) {
        const float* ap = A0 + (size_t)(i0 + am) * FULL + k0 + aj;
#pragma unroll
        for (int s = 0; s < 4; s++) {
            float4 v = *reinterpret_cast<const float4*>(ap + 4 * s);
            sA[am][aj + 4 * s + 0] = wmma::__float_to_tf32(v.x);
            sA[am][aj + 4 * s + 1] = wmma::__float_to_tf32(v.y);
            sA[am][aj + 4 * s + 2] = wmma::__float_to_tf32(v.z);
            sA[am][aj + 4 * s + 3] = wmma::__float_to_tf32(v.w);
        }
        const float* bp = B0 + (size_t)(k0 + bj) * (BSZ * 2 * HN * HD) + bd;
#pragma unroll
        for (int s = 0; s < 2; s++) {
            float4 v = *reinterpret_cast<const float4*>(bp + 4 * s);
            sB[bj][bd + 4 * s + 0] = wmma::__float_to_tf32(v.x);
            sB[bj][bd + 4 * s + 1] = wmma::__float_to_tf32(v.y);
            sB[bj][bd + 4 * s + 2] = wmma::__float_to_tf32(v.z);
            sB[bj][bd + 4 * s + 3] = wmma::__float_to_tf32(v.w);
        }
        __syncthreads();
#pragma unroll
        for (int kk = 0; kk < 4; kk++) {
            wmma::fragment<wmma::matrix_a, 16, 16, 8, wmma::precision::tf32, wmma::row_major> af[2];
            wmma::fragment<wmma::matrix_b, 16, 16, 8, wmma::precision::tf32, wmma::row_major> bf[2];
#pragma unroll
            for (int i = 0; i < 2; i++)
                wmma::load_matrix_sync(af[i], &sA[wm * 32 + i * 16][kk * 8], 40);
#pragma unroll
            for (int j = 0; j < 2; j++)
                wmma::load_matrix_sync(bf[j], &sB[kk * 8][wn * 32 + j * 16], 72);
#pragma unroll
            for (int i = 0; i < 2; i++)
#pragma unroll
                for (int j = 0; j < 2; j++)
                    wmma::mma_sync(acc[i][j], af[i], bf[j], acc[i][j]);
        }
        __syncthreads();
    }
#pragma unroll
    for (int i = 0; i < 2; i++)
#pragma unroll
        for (int j = 0; j < 2; j++)
            wmma::store_matrix_sync(
                ctx + (size_t)((i0 + wm * 32 + i * 16) * BSZ + b) * DMODEL + h * HD + wn * 32 + j * 16,
                acc[i][j], BSZ * DMODEL, wmma::mem_row_major);
}

// ---------------------------------------------------------------------------
// Launch
// ---------------------------------------------------------------------------
extern "C" void kernel_launch(void* const* d_in, const int* in_sizes, int n_in,
                              void* d_out, int out_size)
{
    const float* inputs  = (const float*)d_in[0];
    const float* pos_emb = (const float*)d_in[1];
    const float* full_in = (const float*)d_in[2];
    const float* u       = (const float*)d_in[3];
    const float* v       = (const float*)d_in[4];
    const float* W_kv    = (const float*)d_in[6];
    const float* b_kv    = (const float*)d_in[7];
    const float* W_q     = (const float*)d_in[8];
    const float* b_q     = (const float*)d_in[9];
    const float* W_pos   = (const float*)d_in[10];
    const float* b_proj  = (const float*)d_in[13];
    const float* W_proj  = (const float*)d_in[12];
    float* out = (float*)d_out;

    float *kv, *q, *qu, *qv, *r, *ctx, *scores, *pos, *beff;
    cudaGetSymbolAddress((void**)&kv,     g_kv);
    cudaGetSymbolAddress((void**)&q,      g_q);
    cudaGetSymbolAddress((void**)&qu,     g_qu);
    cudaGetSymbolAddress((void**)&qv,     g_qv);
    cudaGetSymbolAddress((void**)&r,      g_r);
    cudaGetSymbolAddress((void**)&ctx,    g_ctx);
    cudaGetSymbolAddress((void**)&scores, g_scores);
    cudaGetSymbolAddress((void**)&pos,    g_pos);
    cudaGetSymbolAddress((void**)&beff,   g_beff);

    // Projections (bias-free; biases folded/dropped analytically)
    gemm_tf32<<<dim3(2048 / 128, 8192 / 128), 256>>>(full_in, W_kv, kv, 8192, 2048, 1024);
    gemm_tf32<<<dim3(1024 / 128, 4096 / 128), 256>>>(inputs, W_q, q, 4096, 1024, 1024);
    gemm_tf32<<<dim3(1024 / 128, 2048 / 128), 256>>>(pos_emb, W_pos, r, 2048, 1024, 1024);

    // qu/qv (fold b_q + u/v), effective proj bias
    quv_kernel<<<4096, 256>>>(q, b_q, u, v, qu, qv);
    beff_kernel<<<DMODEL / 256, 256>>>(b_kv, W_proj, b_proj, beff);

    // Scores on tensor pipe
    score_tf32<<<dim3(FULL / 128, CUR / 128, ZB), 256>>>(qu, kv, scores, 0);
    score_tf32<<<dim3(FULL / 128, CUR / 128, ZB), 256>>>(qv, r, pos, 1);

    // shift + mask + softmax (in place)
    softmax_kernel<<<dim3(CUR, ZB), 256>>>(scores, pos, scores);

    // ctx = probs @ val
    ctx_tf32<<<dim3(CUR / 128, ZB), 256>>>(scores, kv, ctx);

    // out = ctx @ W_proj, then + b_eff
    gemm_tf32<<<dim3(1024 / 128, 4096 / 128), 256>>>(ctx, W_proj, out, 4096, 1024, 1024);
    bias_add_kernel<<<4096, 256>>>(out, beff);

    (void)in_sizes; (void)n_in; (void)out_size;
}